// round 8
// baseline (speedup 1.0000x reference)
#include <cuda_runtime.h>

// RNG scheme for matching JAX's threefry:
//  0: partitionable split (key = tf((0,42),(0,t))), bits = y0 ^ y1   (modern JAX default)
//  1: partitionable split, bits = y0
//  2: partitionable split, bits = y1
//  3: original (non-partitionable) split + bits = y0
#define RNG_SCHEME 0

#define STEPS 8192
#define HDIM 1024
#define NB 128
#define TPB 256
#define NWARP 8
#define JPB 8

__device__ float g_u[STEPS];
__device__ float g_x0;
__device__ __align__(16) float g_h0[2][HDIM];
__device__ __align__(16) float g_h1[2][HDIM];
__device__ __align__(16) float g_psum[NB];
__device__ unsigned g_bar_count = 0;
__device__ volatile unsigned g_bar_gen = 0;

__device__ __forceinline__ unsigned rotl32(unsigned v, int r) { return (v << r) | (v >> (32 - r)); }

__device__ __forceinline__ void tf2x32(unsigned k0, unsigned k1, unsigned x0, unsigned x1,
                                       unsigned& o0, unsigned& o1) {
    unsigned ks2 = k0 ^ k1 ^ 0x1BD11BDAu;
    x0 += k0; x1 += k1;
#define TFR(r) { x0 += x1; x1 = rotl32(x1, r); x1 ^= x0; }
    TFR(13) TFR(15) TFR(26) TFR(6)
    x0 += k1; x1 += ks2 + 1u;
    TFR(17) TFR(29) TFR(16) TFR(24)
    x0 += ks2; x1 += k0 + 2u;
    TFR(13) TFR(15) TFR(26) TFR(6)
    x0 += k0; x1 += k1 + 3u;
    TFR(17) TFR(29) TFR(16) TFR(24)
    x0 += k1; x1 += ks2 + 4u;
    TFR(13) TFR(15) TFR(26) TFR(6)
    x0 += ks2; x1 += k0 + 5u;
#undef TFR
    o0 = x0; o1 = x1;
}

__global__ void setup_kernel(const float* __restrict__ ctx, const float* __restrict__ W1,
                             const float* __restrict__ b1) {
    int t = blockIdx.x * blockDim.x + threadIdx.x;  // 0..8191
    unsigned ka, kb;
#if RNG_SCHEME <= 2
    tf2x32(0u, 42u, 0u, (unsigned)t, ka, kb);
#else
    {
        unsigned m0 = 2u * (unsigned)t, m1 = 2u * (unsigned)t + 1u;
        unsigned y0, y1;
        unsigned l0 = (m0 < STEPS) ? m0 : m0 - STEPS;
        tf2x32(0u, 42u, l0, l0 + STEPS, y0, y1);
        ka = (m0 < STEPS) ? y0 : y1;
        unsigned l1 = (m1 < STEPS) ? m1 : m1 - STEPS;
        tf2x32(0u, 42u, l1, l1 + STEPS, y0, y1);
        kb = (m1 < STEPS) ? y0 : y1;
    }
#endif
    unsigned y0, y1;
    tf2x32(ka, kb, 0u, 0u, y0, y1);
#if RNG_SCHEME == 0
    unsigned bits = y0 ^ y1;
#elif RNG_SCHEME == 2
    unsigned bits = y1;
#else
    unsigned bits = y0;
#endif
    float u = __uint_as_float((bits >> 9) | 0x3F800000u) - 1.0f;
    g_u[t] = fmaxf(u, 0.0f);

    if (blockIdx.x == 0) {
        __shared__ float red[256];
        int k = threadIdx.x;
        red[k] = W1[k] * ctx[k] + W1[k + 256] * ctx[k + 256];
        __syncthreads();
        if (k == 0) {
            float s = b1[0];
#pragma unroll 16
            for (int i = 0; i < 256; i++) s += red[i];
            g_x0 = s;
        }
    }
}

__device__ __forceinline__ void grid_sync() {
    __syncthreads();
    if (threadIdx.x == 0) {
        __threadfence();
        unsigned gen = g_bar_gen;
        if (atomicAdd(&g_bar_count, 1u) == NB - 1u) {
            g_bar_count = 0u;
            __threadfence();
            g_bar_gen = gen + 1u;
        } else {
            while (g_bar_gen == gen) {}
        }
        __threadfence();
    }
    __syncthreads();
}

__device__ __forceinline__ float sigmoidf(float x) { return 1.0f / (1.0f + expf(-x)); }

__device__ __forceinline__ float dot4(float4 a, float4 b, float acc) {
    acc = fmaf(a.x, b.x, acc);
    acc = fmaf(a.y, b.y, acc);
    acc = fmaf(a.z, b.z, acc);
    acc = fmaf(a.w, b.w, acc);
    return acc;
}

__global__ void __launch_bounds__(TPB) policy_kernel(
    const float* __restrict__ Wih0, const float* __restrict__ Whh0,
    const float* __restrict__ bih0, const float* __restrict__ bhh0,
    const float* __restrict__ Wih1, const float* __restrict__ Whh1,
    const float* __restrict__ bih1, const float* __restrict__ bhh1,
    const float* __restrict__ W2, const float* __restrict__ b2,
    float* __restrict__ out) {
    const int tid = threadIdx.x;
    const int warp = tid >> 5;
    const int lane = tid & 31;
    const int j = blockIdx.x * JPB + warp;  // 0..1023, this warp's hidden index

    __shared__ float4 sh_h0[HDIM / 4];
    __shared__ float4 sh_h1[HDIM / 4];
    __shared__ float sh_w2[NWARP];
    __shared__ float sh_s;

    // Hoisted per-warp constants
    float b1g[4], b0g[4], wih0g[4];
    const float4 *rih1[4], *rhh1[4], *rhh0[4];
#pragma unroll
    for (int g = 0; g < 4; g++) {
        int r = j + (g << 10);
        b1g[g] = __ldg(&bih1[r]) + __ldg(&bhh1[r]);
        b0g[g] = __ldg(&bih0[r]) + __ldg(&bhh0[r]);
        wih0g[g] = __ldg(&Wih0[r]);
        rih1[g] = ((const float4*)Wih1) + (size_t)r * (HDIM / 4) + lane;
        rhh1[g] = ((const float4*)Whh1) + (size_t)r * (HDIM / 4) + lane;
        rhh0[g] = ((const float4*)Whh0) + (size_t)r * (HDIM / 4) + lane;
    }
    const float w2j = __ldg(&W2[j]);
    const float b2v = __ldg(&b2[0]);

    float c0 = 0.0f, c1 = 0.0f, logp = 0.0f;

    // Bootstrap: h0(0) from x0 (h0(-1)=0 so no Whh0 term); h1 state buffer parity 0 = 0.
    {
        float x = g_x0;
        float iv = sigmoidf(fmaf(wih0g[0], x, b0g[0]));
        float fv = sigmoidf(fmaf(wih0g[1], x, b0g[1]));
        float gv = tanhf(fmaf(wih0g[2], x, b0g[2]));
        float ov = sigmoidf(fmaf(wih0g[3], x, b0g[3]));
        c0 = fv * c0 + iv * gv;
        float h0v = ov * tanhf(c0);
        if (lane == 0) {
            g_h0[0][j] = h0v;
            g_h1[0][j] = 0.0f;
        }
    }
    grid_sync();

    for (int t = 0; t < STEPS; t++) {
        const int par = t & 1;
        // Stage h0(t) and h1(t-1) into smem (L2-coherent reads)
        sh_h0[tid] = __ldcg(((const float4*)g_h0[par]) + tid);
        sh_h1[tid] = __ldcg(((const float4*)g_h1[par]) + tid);
        __syncthreads();

        float4 h0r[8], h1r[8];
#pragma unroll
        for (int m = 0; m < 8; m++) {
            h0r[m] = sh_h0[lane + 32 * m];
            h1r[m] = sh_h1[lane + 32 * m];
        }

        // Heavy phase: 12 row-dots per warp (Wih1@h0, Whh1@h1prev, Whh0@h0 [for next step])
        float a2[4], a3[4], a1[4];
#pragma unroll
        for (int g = 0; g < 4; g++) {
            float s2 = 0.0f, s3 = 0.0f, s1 = 0.0f;
#pragma unroll
            for (int m = 0; m < 8; m++) {
                float4 w;
                w = __ldg(rih1[g] + 32 * m); s2 = dot4(w, h0r[m], s2);
                w = __ldg(rhh1[g] + 32 * m); s3 = dot4(w, h1r[m], s3);
                w = __ldg(rhh0[g] + 32 * m); s1 = dot4(w, h0r[m], s1);
            }
            a2[g] = s2; a3[g] = s3; a1[g] = s1;
        }
#pragma unroll
        for (int off = 16; off; off >>= 1) {
#pragma unroll
            for (int g = 0; g < 4; g++) {
                a2[g] += __shfl_xor_sync(0xFFFFFFFFu, a2[g], off);
                a3[g] += __shfl_xor_sync(0xFFFFFFFFu, a3[g], off);
                a1[g] += __shfl_xor_sync(0xFFFFFFFFu, a1[g], off);
            }
        }

        // LSTM layer 1 update: h1(t)
        {
            float iv = sigmoidf(a2[0] + a3[0] + b1g[0]);
            float fv = sigmoidf(a2[1] + a3[1] + b1g[1]);
            float gv = tanhf(a2[2] + a3[2] + b1g[2]);
            float ov = sigmoidf(a2[3] + a3[3] + b1g[3]);
            c1 = fv * c1 + iv * gv;
            float h1v = ov * tanhf(c1);
            if (lane == 0) {
                g_h1[par ^ 1][j] = h1v;
                sh_w2[warp] = w2j * h1v;
            }
        }
        __syncthreads();
        if (tid == 0) {
            float tb = sh_w2[0];
#pragma unroll
            for (int w = 1; w < NWARP; w++) tb += sh_w2[w];
            g_psum[blockIdx.x] = tb;
        }
        grid_sync();

        // Tiny phase: every block redundantly computes p, s (fixed-order sum -> deterministic)
        if (tid == 0) {
            float tot = 0.0f;
            const float4* pp = (const float4*)g_psum;
#pragma unroll
            for (int b = 0; b < NB / 4; b++) {
                float4 v = __ldcg(pp + b);
                tot += v.x; tot += v.y; tot += v.z; tot += v.w;
            }
            float p = sigmoidf(tot + b2v);
            float sv = (g_u[t] < p) ? 1.0f : 0.0f;
            sh_s = sv;
            if (blockIdx.x == 0) {
                out[t] = sv;
                logp += (sv > 0.5f) ? logf(p) : log1pf(-p);
            }
        }
        __syncthreads();
        float sv = sh_s;

        // LSTM layer 0 update for step t+1 (dots a1 were precomputed pre-sync)
        {
            float iv = sigmoidf(fmaf(wih0g[0], sv, a1[0] + b0g[0]));
            float fv = sigmoidf(fmaf(wih0g[1], sv, a1[1] + b0g[1]));
            float gv = tanhf(fmaf(wih0g[2], sv, a1[2] + b0g[2]));
            float ov = sigmoidf(fmaf(wih0g[3], sv, a1[3] + b0g[3]));
            c0 = fv * c0 + iv * gv;
            float h0v = ov * tanhf(c0);
            if (lane == 0) g_h0[par ^ 1][j] = h0v;
        }
        grid_sync();
    }

    if (blockIdx.x == 0 && tid == 0) out[STEPS] = logp;
}

extern "C" void kernel_launch(void* const* d_in, const int* in_sizes, int n_in,
                              void* d_out, int out_size) {
    const float* ctx  = (const float*)d_in[0];
    const float* W1   = (const float*)d_in[1];
    const float* b1   = (const float*)d_in[2];
    const float* Wih0 = (const float*)d_in[3];
    const float* Whh0 = (const float*)d_in[4];
    const float* bih0 = (const float*)d_in[5];
    const float* bhh0 = (const float*)d_in[6];
    const float* Wih1 = (const float*)d_in[7];
    const float* Whh1 = (const float*)d_in[8];
    const float* bih1 = (const float*)d_in[9];
    const float* bhh1 = (const float*)d_in[10];
    const float* W2   = (const float*)d_in[11];
    const float* b2   = (const float*)d_in[12];
    float* out = (float*)d_out;

    setup_kernel<<<32, 256>>>(ctx, W1, b1);
    policy_kernel<<<NB, TPB>>>(Wih0, Whh0, bih0, bhh0, Wih1, Whh1, bih1, bhh1, W2, b2, out);
}

// round 12
// speedup vs baseline: 1.0158x; 1.0158x over previous
#include <cuda_runtime.h>

#define STEPS 8192
#define HDIM 1024
#define NB 128
#define TPB 256
#define NWARP 8
#define JPB 8

__device__ float g_u[STEPS];
__device__ float g_x0;
// Tagged split-word channels: each float = 2 u32 words, each (tag16<<16)|half16.
__device__ unsigned g_h0t[2][HDIM][2];  // [parity][j][hi/lo]
__device__ unsigned g_h1t[2][HDIM][2];  // [parity][j][hi/lo]
__device__ unsigned g_ps[2][NB][2];     // [parity][block][hi/lo]

__device__ __forceinline__ unsigned rotl32(unsigned v, int r) { return (v << r) | (v >> (32 - r)); }

__device__ __forceinline__ void tf2x32(unsigned k0, unsigned k1, unsigned x0, unsigned x1,
                                       unsigned& o0, unsigned& o1) {
    unsigned ks2 = k0 ^ k1 ^ 0x1BD11BDAu;
    x0 += k0; x1 += k1;
#define TFR(r) { x0 += x1; x1 = rotl32(x1, r); x1 ^= x0; }
    TFR(13) TFR(15) TFR(26) TFR(6)
    x0 += k1; x1 += ks2 + 1u;
    TFR(17) TFR(29) TFR(16) TFR(24)
    x0 += ks2; x1 += k0 + 2u;
    TFR(13) TFR(15) TFR(26) TFR(6)
    x0 += k0; x1 += k1 + 3u;
    TFR(17) TFR(29) TFR(16) TFR(24)
    x0 += k1; x1 += ks2 + 4u;
    TFR(13) TFR(15) TFR(26) TFR(6)
    x0 += ks2; x1 += k0 + 5u;
#undef TFR
    o0 = x0; o1 = x1;
}

__global__ void setup_kernel(const float* __restrict__ ctx, const float* __restrict__ W1,
                             const float* __restrict__ b1) {
    int t = blockIdx.x * blockDim.x + threadIdx.x;  // 0..8191
    unsigned ka, kb;
    tf2x32(0u, 42u, 0u, (unsigned)t, ka, kb);
    unsigned y0, y1;
    tf2x32(ka, kb, 0u, 0u, y0, y1);
    unsigned bits = y0 ^ y1;
    float u = __uint_as_float((bits >> 9) | 0x3F800000u) - 1.0f;
    g_u[t] = fmaxf(u, 0.0f);

    // Zero ALL tagged channel words every launch (tags repeat across graph
    // replays; tag 0 is reserved invalid). Stream order puts this before
    // policy_kernel.
    if (t < 2 * HDIM * 2) {
        ((unsigned*)g_h0t)[t] = 0u;  // 4096 words
        ((unsigned*)g_h1t)[t] = 0u;  // 4096 words
    }
    if (t < 2 * NB * 2) ((unsigned*)g_ps)[t] = 0u;  // 512 words

    if (blockIdx.x == 0) {
        __shared__ float red[256];
        int k = threadIdx.x;
        red[k] = W1[k] * ctx[k] + W1[k + 256] * ctx[k + 256];
        __syncthreads();
        if (k == 0) {
            float s = b1[0];
#pragma unroll 16
            for (int i = 0; i < 256; i++) s += red[i];
            g_x0 = s;
        }
    }
}

__device__ __forceinline__ unsigned ldcg_u32(const unsigned* p) {
    unsigned v;
    asm volatile("ld.global.cg.b32 %0, [%1];" : "=r"(v) : "l"(p) : "memory");
    return v;
}
__device__ __forceinline__ void stcg_u32(unsigned* p, unsigned v) {
    asm volatile("st.global.cg.b32 [%0], %1;" :: "l"(p), "r"(v) : "memory");
}

// Publish one float as two tagged 4-byte words (each word single-copy atomic).
__device__ __forceinline__ void pub_f(unsigned* w, float v, unsigned tag) {
    unsigned b = __float_as_uint(v);
    stcg_u32(&w[0], (tag << 16) | (b >> 16));
    stcg_u32(&w[1], (tag << 16) | (b & 0xFFFFu));
}
// Try-read: both halves must carry the exact tag.
__device__ __forceinline__ bool rd_f(const unsigned* w, unsigned tag, float& v) {
    unsigned a = ldcg_u32(&w[0]);
    unsigned b = ldcg_u32(&w[1]);
    if ((a >> 16) != tag || (b >> 16) != tag) return false;
    v = __uint_as_float((a << 16) | (b & 0xFFFFu));
    return true;
}

__device__ __forceinline__ float sigmoidf(float x) { return 1.0f / (1.0f + expf(-x)); }

__device__ __forceinline__ float dot4(float4 a, float4 b, float acc) {
    acc = fmaf(a.x, b.x, acc);
    acc = fmaf(a.y, b.y, acc);
    acc = fmaf(a.z, b.z, acc);
    acc = fmaf(a.w, b.w, acc);
    return acc;
}

__global__ void __launch_bounds__(TPB) policy_kernel(
    const float* __restrict__ Wih0, const float* __restrict__ Whh0,
    const float* __restrict__ bih0, const float* __restrict__ bhh0,
    const float* __restrict__ Wih1, const float* __restrict__ Whh1,
    const float* __restrict__ bih1, const float* __restrict__ bhh1,
    const float* __restrict__ W2, const float* __restrict__ b2,
    float* __restrict__ out) {
    const int tid = threadIdx.x;
    const int warp = tid >> 5;
    const int lane = tid & 31;
    const int bid = blockIdx.x;
    const int j = bid * JPB + warp;  // 0..1023, this warp's hidden index
    const int j0 = tid << 2;         // this thread's 4 staging indices

    __shared__ float4 sh_h0[HDIM / 4];
    __shared__ float4 sh_h1[HDIM / 4];
    __shared__ float sh_w2[NWARP];
    __shared__ float sh_vals[NB];
    __shared__ float sh_s;

    // Hoisted per-warp constants (verbatim R8)
    float b1g[4], b0g[4], wih0g[4];
    const float4 *rih1[4], *rhh1[4], *rhh0[4];
#pragma unroll
    for (int g = 0; g < 4; g++) {
        int r = j + (g << 10);
        b1g[g] = __ldg(&bih1[r]) + __ldg(&bhh1[r]);
        b0g[g] = __ldg(&bih0[r]) + __ldg(&bhh0[r]);
        wih0g[g] = __ldg(&Wih0[r]);
        rih1[g] = ((const float4*)Wih1) + (size_t)r * (HDIM / 4) + lane;
        rhh1[g] = ((const float4*)Whh1) + (size_t)r * (HDIM / 4) + lane;
        rhh0[g] = ((const float4*)Whh0) + (size_t)r * (HDIM / 4) + lane;
    }
    const float w2j = __ldg(&W2[j]);
    const float b2v = __ldg(&b2[0]);

    float c0 = 0.0f, c1 = 0.0f, logp = 0.0f;

    // ---- Bootstrap (verbatim R8 math): h0(0) from x0; h1(0)=0. Tag=1. ----
    {
        float x = g_x0;
        float iv = sigmoidf(fmaf(wih0g[0], x, b0g[0]));
        float fv = sigmoidf(fmaf(wih0g[1], x, b0g[1]));
        float gv = tanhf(fmaf(wih0g[2], x, b0g[2]));
        float ov = sigmoidf(fmaf(wih0g[3], x, b0g[3]));
        c0 = fv * c0 + iv * gv;
        float h0v = ov * tanhf(c0);
        if (lane == 0) {
            pub_f(g_h0t[1][j], h0v, 1u);
            pub_f(g_h1t[1][j], 0.0f, 1u);
        }
    }

    for (int t = 0; t < STEPS; t++) {
        const unsigned tagin = (unsigned)(t + 1);   // consumed this step
        const unsigned tagout = (unsigned)(t + 2);  // produced this step
        const int parin = (t + 1) & 1;
        const int parout = (t + 2) & 1;

        // ---- Stage: poll tagged h words of this step into smem ----
        {
            float v0[4], v1[4];
            unsigned pend = 0xFFu;
            const unsigned(*h0src)[2] = g_h0t[parin];
            const unsigned(*h1src)[2] = g_h1t[parin];
            while (pend) {
#pragma unroll
                for (int k = 0; k < 4; k++) {
                    if (pend & (1u << k))
                        if (rd_f(h0src[j0 + k], tagin, v0[k])) pend &= ~(1u << k);
                }
#pragma unroll
                for (int k = 0; k < 4; k++) {
                    if (pend & (1u << (4 + k)))
                        if (rd_f(h1src[j0 + k], tagin, v1[k])) pend &= ~(1u << (4 + k));
                }
            }
            sh_h0[tid] = make_float4(v0[0], v0[1], v0[2], v0[3]);
            sh_h1[tid] = make_float4(v1[0], v1[1], v1[2], v1[3]);
        }
        __syncthreads();

        float4 h0r[8], h1r[8];
#pragma unroll
        for (int m = 0; m < 8; m++) {
            h0r[m] = sh_h0[lane + 32 * m];
            h1r[m] = sh_h1[lane + 32 * m];
        }

        // ---- Heavy phase: 12 row-dots per warp (verbatim R8) ----
        float a2[4], a3[4], a1[4];
#pragma unroll
        for (int g = 0; g < 4; g++) {
            float s2 = 0.0f, s3 = 0.0f, s1 = 0.0f;
#pragma unroll
            for (int m = 0; m < 8; m++) {
                float4 w;
                w = __ldg(rih1[g] + 32 * m); s2 = dot4(w, h0r[m], s2);
                w = __ldg(rhh1[g] + 32 * m); s3 = dot4(w, h1r[m], s3);
                w = __ldg(rhh0[g] + 32 * m); s1 = dot4(w, h0r[m], s1);
            }
            a2[g] = s2; a3[g] = s3; a1[g] = s1;
        }
#pragma unroll
        for (int off = 16; off; off >>= 1) {
#pragma unroll
            for (int g = 0; g < 4; g++) {
                a2[g] += __shfl_xor_sync(0xFFFFFFFFu, a2[g], off);
                a3[g] += __shfl_xor_sync(0xFFFFFFFFu, a3[g], off);
                a1[g] += __shfl_xor_sync(0xFFFFFFFFu, a1[g], off);
            }
        }

        // ---- LSTM layer 1 update: h1(t) (verbatim R8); publish tagged ----
        {
            float iv = sigmoidf(a2[0] + a3[0] + b1g[0]);
            float fv = sigmoidf(a2[1] + a3[1] + b1g[1]);
            float gv = tanhf(a2[2] + a3[2] + b1g[2]);
            float ov = sigmoidf(a2[3] + a3[3] + b1g[3]);
            c1 = fv * c1 + iv * gv;
            float h1v = ov * tanhf(c1);
            if (lane == 0) {
                sh_w2[warp] = w2j * h1v;
                pub_f(g_h1t[parout][j], h1v, tagout);
            }
        }
        __syncthreads();

        // ---- Publish psi partial (fixed-order 8-warp sum), tagged ----
        if (tid == 0) {
            float tb = sh_w2[0];
#pragma unroll
            for (int w = 1; w < NWARP; w++) tb += sh_w2[w];
            pub_f(g_ps[parout][bid], tb, tagout);
        }

        // ---- Poll all 128 psi partials of this step ----
        if (tid < NB) {
            float v;
            while (!rd_f(g_ps[parout][tid], tagout, v)) {}
            sh_vals[tid] = v;
        }
        __syncthreads();

        // ---- Tiny phase: fixed-order sum -> p, sample; all blocks agree ----
        if (tid == 0) {
            float tot = 0.0f;
#pragma unroll 8
            for (int b = 0; b < NB; b++) tot += sh_vals[b];
            float p = sigmoidf(tot + b2v);
            float sv = (g_u[t] < p) ? 1.0f : 0.0f;
            sh_s = sv;
            if (bid == 0) {
                out[t] = sv;
                logp += (sv > 0.5f) ? logf(p) : log1pf(-p);
            }
        }
        __syncthreads();
        float sv = sh_s;

        // ---- LSTM layer 0 for step t+1 (verbatim R8: realized sv) ----
        {
            float iv = sigmoidf(fmaf(wih0g[0], sv, a1[0] + b0g[0]));
            float fv = sigmoidf(fmaf(wih0g[1], sv, a1[1] + b0g[1]));
            float gv = tanhf(fmaf(wih0g[2], sv, a1[2] + b0g[2]));
            float ov = sigmoidf(fmaf(wih0g[3], sv, a1[3] + b0g[3]));
            c0 = fv * c0 + iv * gv;
            float h0v = ov * tanhf(c0);
            if (lane == 0) pub_f(g_h0t[parout][j], h0v, tagout);
        }
    }

    if (bid == 0 && tid == 0) out[STEPS] = logp;
}

extern "C" void kernel_launch(void* const* d_in, const int* in_sizes, int n_in,
                              void* d_out, int out_size) {
    const float* ctx  = (const float*)d_in[0];
    const float* W1   = (const float*)d_in[1];
    const float* b1   = (const float*)d_in[2];
    const float* Wih0 = (const float*)d_in[3];
    const float* Whh0 = (const float*)d_in[4];
    const float* bih0 = (const float*)d_in[5];
    const float* bhh0 = (const float*)d_in[6];
    const float* Wih1 = (const float*)d_in[7];
    const float* Whh1 = (const float*)d_in[8];
    const float* bih1 = (const float*)d_in[9];
    const float* bhh1 = (const float*)d_in[10];
    const float* W2   = (const float*)d_in[11];
    const float* b2   = (const float*)d_in[12];
    float* out = (float*)d_out;

    setup_kernel<<<32, 256>>>(ctx, W1, b1);
    policy_kernel<<<NB, TPB>>>(Wih0, Whh0, bih0, bhh0, Wih1, Whh1, bih1, bhh1, W2, b2, out);
}